// round 4
// baseline (speedup 1.0000x reference)
#include <cuda_runtime.h>
#include <cuda_bf16.h>
#include <math.h>

#define NN 4096
#define IN_DIM 256
#define HIDDEN 512
#define CLASSES 256
#define HEADS 4
#define HD 64
#define EE 131072

// ---------------- scratch (single device global; offsets are compile-time) ----
#define OFF_DINV 0L
#define OFF_H1   (OFF_DINV + NN)
#define OFF_AGG1 (OFF_H1   + (long)NN * HIDDEN)
#define OFF_H2   (OFF_AGG1 + (long)NN * HIDDEN)
#define OFF_AGG2 (OFF_H2   + (long)NN * HIDDEN)
#define OFF_GNN  (OFF_AGG2 + (long)NN * HIDDEN)
#define OFF_QKV  (OFF_GNN  + (long)NN * CLASSES)
#define OFF_ATTN (OFF_QKV  + (long)NN * 3 * IN_DIM)
#define OFF_XTF  (OFF_ATTN + (long)NN * IN_DIM)
#define SCRATCH_TOTAL (OFF_XTF + (long)NN * IN_DIM)

__device__ float g_scratch[SCRATCH_TOTAL];

// ---------------- degree / norm ----------------
__global__ void deg_init_kernel() {
    int i = blockIdx.x * blockDim.x + threadIdx.x;
    if (i < NN) g_scratch[OFF_DINV + i] = 1.0f;  // self loop
}
__global__ void deg_count_kernel(const int* __restrict__ ei) {
    int i = blockIdx.x * blockDim.x + threadIdx.x;
    if (i < EE) atomicAdd(&g_scratch[OFF_DINV + ei[EE + i]], 1.0f);
}
__global__ void deg_finalize_kernel() {
    int i = blockIdx.x * blockDim.x + threadIdx.x;
    if (i < NN) g_scratch[OFF_DINV + i] = rsqrtf(g_scratch[OFF_DINV + i]);
}

// ---------------- generic tiled fp32 GEMM ----------------
// A = Aext ? Aext : g_scratch+aoff ; C likewise. B/bias always runtime inputs.
// C[M,Nd] = A[M,K] @ (TRANSB ? B[Nd,K]^T : B[K,Nd]) (+bias) (+add from scratch) (relu?)
template <bool TRANSB, bool RELU, bool HASBIAS, bool HASADD>
__global__ void gemm_kernel(const float* __restrict__ Aext, long aoff,
                            const float* __restrict__ B,
                            const float* __restrict__ bias,
                            long addoff,
                            float* __restrict__ Cext, long coff,
                            int M, int K, int Nd) {
    const float* __restrict__ A = Aext ? Aext : (const float*)(g_scratch + aoff);
    float* __restrict__ C = Cext ? Cext : (g_scratch + coff);
    const float* __restrict__ addsrc = g_scratch + (HASADD ? addoff : 0);

    __shared__ float As[16][64];
    __shared__ float Bs[16][64];
    const int tid = threadIdx.x;
    const int tx = tid & 15, ty = tid >> 4;
    const int m0 = blockIdx.y * 64, n0 = blockIdx.x * 64;

    float acc[4][4];
#pragma unroll
    for (int i = 0; i < 4; i++)
#pragma unroll
        for (int j = 0; j < 4; j++) acc[i][j] = 0.0f;

    for (int k0 = 0; k0 < K; k0 += 16) {
        {   // A tile -> As[k][m] (transposed stage)
            int r = tid >> 2;
            int kq = (tid & 3) * 4;
            float4 v = *(const float4*)(A + (size_t)(m0 + r) * K + k0 + kq);
            As[kq + 0][r] = v.x; As[kq + 1][r] = v.y;
            As[kq + 2][r] = v.z; As[kq + 3][r] = v.w;
        }
        if (TRANSB) {
            int n = tid >> 2;
            int kq = (tid & 3) * 4;
            float4 v = *(const float4*)(B + (size_t)(n0 + n) * K + k0 + kq);
            Bs[kq + 0][n] = v.x; Bs[kq + 1][n] = v.y;
            Bs[kq + 2][n] = v.z; Bs[kq + 3][n] = v.w;
        } else {
            int kr = tid >> 4;
            int n4 = (tid & 15) * 4;
            float4 v = *(const float4*)(B + (size_t)(k0 + kr) * Nd + n0 + n4);
            *(float4*)&Bs[kr][n4] = v;
        }
        __syncthreads();
#pragma unroll
        for (int kk = 0; kk < 16; kk++) {
            float av[4], bv[4];
            *(float4*)av = *(const float4*)&As[kk][ty * 4];
            *(float4*)bv = *(const float4*)&Bs[kk][tx * 4];
#pragma unroll
            for (int i = 0; i < 4; i++)
#pragma unroll
                for (int j = 0; j < 4; j++) acc[i][j] += av[i] * bv[j];
        }
        __syncthreads();
    }

#pragma unroll
    for (int i = 0; i < 4; i++) {
        int r = m0 + ty * 4 + i;
#pragma unroll
        for (int j = 0; j < 4; j++) {
            int c = n0 + tx * 4 + j;
            float v = acc[i][j];
            if (HASBIAS) v += bias[c];
            if (HASADD) v += addsrc[(size_t)r * Nd + c];
            if (RELU) v = fmaxf(v, 0.0f);
            C[(size_t)r * Nd + c] = v;
        }
    }
}

// ---------------- GCN aggregation ----------------
// agg[n,f] = h[n,f]*dinv[n]^2 + bias[f]   (self-loop term + bias)
__global__ void selfloop_bias_kernel(long hoff, const float* __restrict__ b,
                                     long aggoff, int F) {
    const float* __restrict__ h = g_scratch + hoff;
    float* __restrict__ agg = g_scratch + aggoff;
    const float* __restrict__ dinv = g_scratch + OFF_DINV;
    int idx = blockIdx.x * blockDim.x + threadIdx.x;
    if (idx >= NN * F) return;
    int n = idx / F;
    int f = idx - n * F;
    float w = dinv[n] * dinv[n];
    agg[idx] = h[idx] * w + b[f];
}

// edge scatter: agg[dst] += h[src] * dinv[src]*dinv[dst]
__global__ void scatter_kernel(long hoff, const int* __restrict__ ei,
                               long aggoff, int F) {
    const float* __restrict__ h = g_scratch + hoff;
    float* __restrict__ agg = g_scratch + aggoff;
    const float* __restrict__ dinv = g_scratch + OFF_DINV;
    int idx = blockIdx.x * blockDim.x + threadIdx.x;
    int cpr = F >> 2;
    if (idx >= EE * cpr) return;
    int e = idx / cpr;
    int c = (idx - e * cpr) * 4;
    int src = ei[e];
    int dst = ei[EE + e];
    float w = dinv[src] * dinv[dst];
    float4 v = *(const float4*)(h + (size_t)src * F + c);
    float* p = agg + (size_t)dst * F + c;
    atomicAdd(p + 0, v.x * w);
    atomicAdd(p + 1, v.y * w);
    atomicAdd(p + 2, v.z * w);
    atomicAdd(p + 3, v.w * w);
}

__global__ void relu_kernel(long off, int n) {
    int i = blockIdx.x * blockDim.x + threadIdx.x;
    if (i < n) g_scratch[off + i] = fmaxf(g_scratch[off + i], 0.0f);
}

// ---------------- flash attention (fp32, online softmax) ----------------
// qkv in scratch: [N, 768] (q|k|v). out -> scratch attn [N, 256].
// grid (N/64, HEADS), 256 threads. BQ=64, BK=32.
__global__ void flash_attn_kernel() {
    const float* __restrict__ qkv = g_scratch + OFF_QKV;
    float* __restrict__ outp = g_scratch + OFF_ATTN;
    const int head = blockIdx.y;
    const int q0 = blockIdx.x * 64;
    const int tid = threadIdx.x;
    const int tx = tid & 15;
    const int ty = tid >> 4;

    __shared__ float Qs[64][65];
    __shared__ float Ks[32][65];
    __shared__ float Vs[32][65];
    __shared__ float Ps[64][33];

    // load Q tile: 64 rows x 64 floats
#pragma unroll
    for (int p = 0; p < 4; p++) {
        int idx = p * 256 + tid;
        int r = idx >> 4;
        int c4 = (idx & 15) * 4;
        float4 v = *(const float4*)(qkv + (size_t)(q0 + r) * 768 + head * 64 + c4);
        Qs[r][c4 + 0] = v.x; Qs[r][c4 + 1] = v.y; Qs[r][c4 + 2] = v.z; Qs[r][c4 + 3] = v.w;
    }

    float m_i[4], l_i[4], o[4][4];
#pragma unroll
    for (int i = 0; i < 4; i++) {
        m_i[i] = -1e30f;
        l_i[i] = 0.0f;
#pragma unroll
        for (int j = 0; j < 4; j++) o[i][j] = 0.0f;
    }

    for (int kb = 0; kb < NN / 32; kb++) {
        __syncthreads();
        // load K,V tiles: 32 rows x 64 floats each
#pragma unroll
        for (int p = 0; p < 2; p++) {
            int idx = p * 256 + tid;
            int r = idx >> 4;
            int c4 = (idx & 15) * 4;
            const float* kp = qkv + (size_t)(kb * 32 + r) * 768 + 256 + head * 64 + c4;
            float4 kv = *(const float4*)kp;
            Ks[r][c4 + 0] = kv.x; Ks[r][c4 + 1] = kv.y; Ks[r][c4 + 2] = kv.z; Ks[r][c4 + 3] = kv.w;
            float4 vv = *(const float4*)(kp + 256);
            Vs[r][c4 + 0] = vv.x; Vs[r][c4 + 1] = vv.y; Vs[r][c4 + 2] = vv.z; Vs[r][c4 + 3] = vv.w;
        }
        __syncthreads();

        // S = Q K^T * 0.125 : thread tile 4 rows x 2 cols
        float s[4][2];
#pragma unroll
        for (int i = 0; i < 4; i++) { s[i][0] = 0.0f; s[i][1] = 0.0f; }
#pragma unroll
        for (int d = 0; d < 64; d++) {
            float b0 = Ks[tx * 2 + 0][d];
            float b1 = Ks[tx * 2 + 1][d];
#pragma unroll
            for (int i = 0; i < 4; i++) {
                float a = Qs[ty * 4 + i][d];
                s[i][0] += a * b0;
                s[i][1] += a * b1;
            }
        }

        // online softmax, row reduction across the 16 lanes sharing ty
#pragma unroll
        for (int i = 0; i < 4; i++) {
            s[i][0] *= 0.125f; s[i][1] *= 0.125f;
            float mc = fmaxf(s[i][0], s[i][1]);
#pragma unroll
            for (int off = 8; off >= 1; off >>= 1)
                mc = fmaxf(mc, __shfl_xor_sync(0xffffffffu, mc, off));
            float mn = fmaxf(m_i[i], mc);
            float p0 = __expf(s[i][0] - mn);
            float p1 = __expf(s[i][1] - mn);
            float ps = p0 + p1;
#pragma unroll
            for (int off = 8; off >= 1; off >>= 1)
                ps += __shfl_xor_sync(0xffffffffu, ps, off);
            float alpha = __expf(m_i[i] - mn);
            l_i[i] = l_i[i] * alpha + ps;
            m_i[i] = mn;
#pragma unroll
            for (int j = 0; j < 4; j++) o[i][j] *= alpha;
            Ps[ty * 4 + i][tx * 2 + 0] = p0;
            Ps[ty * 4 + i][tx * 2 + 1] = p1;
        }
        __syncthreads();

        // O += P V : thread tile 4 rows x 4 d-cols
#pragma unroll
        for (int k = 0; k < 32; k++) {
            float v0 = Vs[k][tx * 4 + 0];
            float v1 = Vs[k][tx * 4 + 1];
            float v2 = Vs[k][tx * 4 + 2];
            float v3 = Vs[k][tx * 4 + 3];
#pragma unroll
            for (int i = 0; i < 4; i++) {
                float p = Ps[ty * 4 + i][k];
                o[i][0] += p * v0;
                o[i][1] += p * v1;
                o[i][2] += p * v2;
                o[i][3] += p * v3;
            }
        }
    }

#pragma unroll
    for (int i = 0; i < 4; i++) {
        float inv = 1.0f / l_i[i];
        int r = q0 + ty * 4 + i;
#pragma unroll
        for (int j = 0; j < 4; j++)
            outp[(size_t)r * IN_DIM + head * 64 + tx * 4 + j] = o[i][j] * inv;
    }
}

// ---------------- launch ----------------
extern "C" void kernel_launch(void* const* d_in, const int* in_sizes, int n_in,
                              void* d_out, int out_size) {
    const float* x          = (const float*)d_in[0];
    const int*   ei         = (const int*)d_in[1];
    const float* gcn1_w     = (const float*)d_in[2];
    const float* gcn1_b     = (const float*)d_in[3];
    const float* gcn2_w     = (const float*)d_in[4];
    const float* gcn2_b     = (const float*)d_in[5];
    const float* lin_w      = (const float*)d_in[6];
    const float* lin_b      = (const float*)d_in[7];
    const float* in_proj_w  = (const float*)d_in[8];
    const float* in_proj_b  = (const float*)d_in[9];
    const float* out_proj_w = (const float*)d_in[10];
    const float* out_proj_b = (const float*)d_in[11];
    const float* proj_w     = (const float*)d_in[12];
    const float* proj_b     = (const float*)d_in[13];
    float* out = (float*)d_out;

    // degree / normalization
    deg_init_kernel<<<NN / 256, 256>>>();
    deg_count_kernel<<<EE / 256, 256>>>(ei);
    deg_finalize_kernel<<<NN / 256, 256>>>();

    // ---- GNN branch ----
    // h1 = x @ gcn1_w
    gemm_kernel<false, false, false, false><<<dim3(HIDDEN / 64, NN / 64), 256>>>(
        x, 0L, gcn1_w, nullptr, 0L, nullptr, OFF_H1, NN, IN_DIM, HIDDEN);
    selfloop_bias_kernel<<<(NN * HIDDEN) / 256, 256>>>(OFF_H1, gcn1_b, OFF_AGG1, HIDDEN);
    scatter_kernel<<<(EE * (HIDDEN / 4)) / 256, 256>>>(OFF_H1, ei, OFF_AGG1, HIDDEN);
    relu_kernel<<<(NN * HIDDEN) / 256, 256>>>(OFF_AGG1, NN * HIDDEN);

    // h2 = agg1 @ gcn2_w
    gemm_kernel<false, false, false, false><<<dim3(HIDDEN / 64, NN / 64), 256>>>(
        nullptr, OFF_AGG1, gcn2_w, nullptr, 0L, nullptr, OFF_H2, NN, HIDDEN, HIDDEN);
    selfloop_bias_kernel<<<(NN * HIDDEN) / 256, 256>>>(OFF_H2, gcn2_b, OFF_AGG2, HIDDEN);
    scatter_kernel<<<(EE * (HIDDEN / 4)) / 256, 256>>>(OFF_H2, ei, OFF_AGG2, HIDDEN);
    relu_kernel<<<(NN * HIDDEN) / 256, 256>>>(OFF_AGG2, NN * HIDDEN);

    // gnn = agg2 @ lin_w + lin_b
    gemm_kernel<false, false, true, false><<<dim3(CLASSES / 64, NN / 64), 256>>>(
        nullptr, OFF_AGG2, lin_w, lin_b, 0L, nullptr, OFF_GNN, NN, HIDDEN, CLASSES);

    // ---- Transformer branch ----
    // qkv = x @ in_proj_w^T + in_proj_b
    gemm_kernel<true, false, true, false><<<dim3((3 * IN_DIM) / 64, NN / 64), 256>>>(
        x, 0L, in_proj_w, in_proj_b, 0L, nullptr, OFF_QKV, NN, IN_DIM, 3 * IN_DIM);

    flash_attn_kernel<<<dim3(NN / 64, HEADS), 256>>>();

    // xtf = attn @ out_proj_w^T + out_proj_b
    gemm_kernel<true, false, true, false><<<dim3(IN_DIM / 64, NN / 64), 256>>>(
        nullptr, OFF_ATTN, out_proj_w, out_proj_b, 0L, nullptr, OFF_XTF, NN, IN_DIM, IN_DIM);

    // out = relu(gnn + xtf @ proj_w + proj_b)
    gemm_kernel<false, true, true, true><<<dim3(CLASSES / 64, NN / 64), 256>>>(
        nullptr, OFF_XTF, proj_w, proj_b, OFF_GNN, out, 0L, NN, IN_DIM, CLASSES);
}

// round 5
// speedup vs baseline: 1.8548x; 1.8548x over previous
#include <cuda_runtime.h>
#include <cuda_bf16.h>
#include <math.h>
#include <stdint.h>

#define NN 4096
#define IN_DIM 256
#define HIDDEN 512
#define CLASSES 256
#define HEADS 4
#define HD 64
#define EE 131072

// ---------------- scratch (single device global; offsets are compile-time) ----
#define OFF_DINV 0L
#define OFF_H1   (OFF_DINV + NN)
#define OFF_AGG1 (OFF_H1   + (long)NN * HIDDEN)
#define OFF_H2   (OFF_AGG1 + (long)NN * HIDDEN)
#define OFF_AGG2 (OFF_H2   + (long)NN * HIDDEN)
#define OFF_GNN  (OFF_AGG2 + (long)NN * HIDDEN)
#define OFF_QKV  (OFF_GNN  + (long)NN * CLASSES)
#define OFF_ATTN (OFF_QKV  + (long)NN * 3 * IN_DIM)
#define OFF_XTF  (OFF_ATTN + (long)NN * IN_DIM)
#define SCRATCH_TOTAL (OFF_XTF + (long)NN * IN_DIM)

__device__ __align__(16) float g_scratch[SCRATCH_TOTAL];
__device__ __align__(16) __nv_bfloat16 g_qkvh[(long)NN * 3 * IN_DIM];

// ---------------- degree / norm ----------------
__global__ void deg_init_kernel() {
    int i = blockIdx.x * blockDim.x + threadIdx.x;
    if (i < NN) g_scratch[OFF_DINV + i] = 1.0f;  // self loop
}
__global__ void deg_count_kernel(const int* __restrict__ ei) {
    int i = blockIdx.x * blockDim.x + threadIdx.x;
    if (i < EE) atomicAdd(&g_scratch[OFF_DINV + ei[EE + i]], 1.0f);
}
__global__ void deg_finalize_kernel() {
    int i = blockIdx.x * blockDim.x + threadIdx.x;
    if (i < NN) g_scratch[OFF_DINV + i] = rsqrtf(g_scratch[OFF_DINV + i]);
}

// ---------------- generic tiled fp32 GEMM ----------------
template <bool TRANSB, bool RELU, bool HASBIAS, bool HASADD>
__global__ void gemm_kernel(const float* __restrict__ Aext, long aoff,
                            const float* __restrict__ B,
                            const float* __restrict__ bias,
                            long addoff,
                            float* __restrict__ Cext, long coff,
                            int M, int K, int Nd) {
    const float* __restrict__ A = Aext ? Aext : (const float*)(g_scratch + aoff);
    float* __restrict__ C = Cext ? Cext : (g_scratch + coff);
    const float* __restrict__ addsrc = g_scratch + (HASADD ? addoff : 0);

    __shared__ float As[16][64];
    __shared__ float Bs[16][64];
    const int tid = threadIdx.x;
    const int tx = tid & 15, ty = tid >> 4;
    const int m0 = blockIdx.y * 64, n0 = blockIdx.x * 64;

    float acc[4][4];
#pragma unroll
    for (int i = 0; i < 4; i++)
#pragma unroll
        for (int j = 0; j < 4; j++) acc[i][j] = 0.0f;

    for (int k0 = 0; k0 < K; k0 += 16) {
        {   // A tile -> As[k][m] (transposed stage)
            int r = tid >> 2;
            int kq = (tid & 3) * 4;
            float4 v = *(const float4*)(A + (size_t)(m0 + r) * K + k0 + kq);
            As[kq + 0][r] = v.x; As[kq + 1][r] = v.y;
            As[kq + 2][r] = v.z; As[kq + 3][r] = v.w;
        }
        if (TRANSB) {
            int n = tid >> 2;
            int kq = (tid & 3) * 4;
            float4 v = *(const float4*)(B + (size_t)(n0 + n) * K + k0 + kq);
            Bs[kq + 0][n] = v.x; Bs[kq + 1][n] = v.y;
            Bs[kq + 2][n] = v.z; Bs[kq + 3][n] = v.w;
        } else {
            int kr = tid >> 4;
            int n4 = (tid & 15) * 4;
            float4 v = *(const float4*)(B + (size_t)(k0 + kr) * Nd + n0 + n4);
            *(float4*)&Bs[kr][n4] = v;
        }
        __syncthreads();
#pragma unroll
        for (int kk = 0; kk < 16; kk++) {
            float av[4], bv[4];
            *(float4*)av = *(const float4*)&As[kk][ty * 4];
            *(float4*)bv = *(const float4*)&Bs[kk][tx * 4];
#pragma unroll
            for (int i = 0; i < 4; i++)
#pragma unroll
                for (int j = 0; j < 4; j++) acc[i][j] += av[i] * bv[j];
        }
        __syncthreads();
    }

#pragma unroll
    for (int i = 0; i < 4; i++) {
        int r = m0 + ty * 4 + i;
#pragma unroll
        for (int j = 0; j < 4; j++) {
            int c = n0 + tx * 4 + j;
            float v = acc[i][j];
            if (HASBIAS) v += bias[c];
            if (HASADD) v += addsrc[(size_t)r * Nd + c];
            if (RELU) v = fmaxf(v, 0.0f);
            C[(size_t)r * Nd + c] = v;
        }
    }
}

// ---------------- GCN aggregation ----------------
__global__ void selfloop_bias_kernel(long hoff, const float* __restrict__ b,
                                     long aggoff, int F) {
    const float* __restrict__ h = g_scratch + hoff;
    float* __restrict__ agg = g_scratch + aggoff;
    const float* __restrict__ dinv = g_scratch + OFF_DINV;
    int idx = blockIdx.x * blockDim.x + threadIdx.x;
    if (idx >= NN * F) return;
    int n = idx / F;
    int f = idx - n * F;
    float w = dinv[n] * dinv[n];
    agg[idx] = h[idx] * w + b[f];
}

__global__ void scatter_kernel(long hoff, const int* __restrict__ ei,
                               long aggoff, int F) {
    const float* __restrict__ h = g_scratch + hoff;
    float* __restrict__ agg = g_scratch + aggoff;
    const float* __restrict__ dinv = g_scratch + OFF_DINV;
    int idx = blockIdx.x * blockDim.x + threadIdx.x;
    int cpr = F >> 2;
    if (idx >= EE * cpr) return;
    int e = idx / cpr;
    int c = (idx - e * cpr) * 4;
    int src = ei[e];
    int dst = ei[EE + e];
    float w = dinv[src] * dinv[dst];
    float4 v = *(const float4*)(h + (size_t)src * F + c);
    float* p = agg + (size_t)dst * F + c;
    atomicAdd(p + 0, v.x * w);
    atomicAdd(p + 1, v.y * w);
    atomicAdd(p + 2, v.z * w);
    atomicAdd(p + 3, v.w * w);
}

__global__ void relu_kernel(long off, int n) {
    int i = blockIdx.x * blockDim.x + threadIdx.x;
    if (i < n) g_scratch[off + i] = fmaxf(g_scratch[off + i], 0.0f);
}

// ---------------- qkv fp32 -> bf16 conversion ----------------
__global__ void cvt_qkv_kernel() {
    int i = blockIdx.x * blockDim.x + threadIdx.x;  // over NN*768/2
    float2 v = *(const float2*)&g_scratch[OFF_QKV + 2L * i];
    ((__nv_bfloat162*)g_qkvh)[i] = __floats2bfloat162_rn(v.x, v.y);
}

// ---------------- bf16 tensor-core flash attention ----------------
__device__ __forceinline__ void mma_bf16(float c[4], uint32_t a0, uint32_t a1,
                                         uint32_t a2, uint32_t a3,
                                         uint32_t b0, uint32_t b1) {
    asm volatile(
        "mma.sync.aligned.m16n8k16.row.col.f32.bf16.bf16.f32 "
        "{%0,%1,%2,%3},{%4,%5,%6,%7},{%8,%9},{%0,%1,%2,%3};\n"
        : "+f"(c[0]), "+f"(c[1]), "+f"(c[2]), "+f"(c[3])
        : "r"(a0), "r"(a1), "r"(a2), "r"(a3), "r"(b0), "r"(b1));
}

#define FA_PITCH 72

__global__ __launch_bounds__(128) void flash_attn_bf16_kernel() {
    const __nv_bfloat16* __restrict__ qkvh = g_qkvh;
    float* __restrict__ outp = g_scratch + OFF_ATTN;
    const int head = blockIdx.y;
    const int q0 = blockIdx.x * 64;
    const int tid = threadIdx.x;
    const int warp = tid >> 5;
    const int lane = tid & 31;
    const int quad = lane >> 2;
    const int qd = lane & 3;

    __shared__ __align__(16) __nv_bfloat16 Qs[64][FA_PITCH];
    __shared__ __align__(16) __nv_bfloat16 Ks[64][FA_PITCH];
    __shared__ __align__(16) __nv_bfloat16 Vt[64][FA_PITCH];
    __shared__ __align__(16) __nv_bfloat16 Ps[64][FA_PITCH];

    // load Q tile (64 rows x 64 cols) once
#pragma unroll
    for (int ch = 0; ch < 4; ch++) {
        int idx = ch * 128 + tid;
        int r = idx >> 3;
        int c = (idx & 7) * 8;
        *(uint4*)&Qs[r][c] =
            *(const uint4*)&qkvh[(size_t)(q0 + r) * 768 + head * 64 + c];
    }

    float m0r = -1e30f, m1r = -1e30f;
    float l0r = 0.0f, l1r = 0.0f;
    float o[8][4];
#pragma unroll
    for (int nt = 0; nt < 8; nt++)
#pragma unroll
        for (int j = 0; j < 4; j++) o[nt][j] = 0.0f;

    const int qrowA = warp * 16 + quad;
    const int qrowB = qrowA + 8;

    for (int kb = 0; kb < NN / 64; kb++) {
        int kbase = kb * 64;
        __syncthreads();
        // stage K tile [kcol][hd]
#pragma unroll
        for (int ch = 0; ch < 4; ch++) {
            int idx = ch * 128 + tid;
            int r = idx >> 3;
            int c = (idx & 7) * 8;
            *(uint4*)&Ks[r][c] =
                *(const uint4*)&qkvh[(size_t)(kbase + r) * 768 + 256 + head * 64 + c];
        }
        // stage V transposed: Vt[d][krow]
        {
            int r = tid & 63;
            int d0 = (tid >> 6) * 32;
#pragma unroll
            for (int u = 0; u < 4; u++) {
                uint4 vv = *(const uint4*)&qkvh[(size_t)(kbase + r) * 768 + 512 +
                                                head * 64 + d0 + u * 8];
                __nv_bfloat16 tmp[8];
                *(uint4*)tmp = vv;
#pragma unroll
                for (int j = 0; j < 8; j++) Vt[d0 + u * 8 + j][r] = tmp[j];
            }
        }
        __syncthreads();

        // ---- S = Q K^T ----
        float sc[8][4];
#pragma unroll
        for (int nt = 0; nt < 8; nt++)
#pragma unroll
            for (int j = 0; j < 4; j++) sc[nt][j] = 0.0f;

#pragma unroll
        for (int ks = 0; ks < 4; ks++) {
            int k0 = ks * 16;
            uint32_t a0 = *(const uint32_t*)&Qs[qrowA][k0 + qd * 2];
            uint32_t a1 = *(const uint32_t*)&Qs[qrowB][k0 + qd * 2];
            uint32_t a2 = *(const uint32_t*)&Qs[qrowA][k0 + qd * 2 + 8];
            uint32_t a3 = *(const uint32_t*)&Qs[qrowB][k0 + qd * 2 + 8];
#pragma unroll
            for (int nt = 0; nt < 8; nt++) {
                uint32_t b0 = *(const uint32_t*)&Ks[nt * 8 + quad][k0 + qd * 2];
                uint32_t b1 = *(const uint32_t*)&Ks[nt * 8 + quad][k0 + qd * 2 + 8];
                mma_bf16(sc[nt], a0, a1, a2, a3, b0, b1);
            }
        }

        // ---- online softmax (scale 0.125) ----
        float mA = -1e30f, mB = -1e30f;
#pragma unroll
        for (int nt = 0; nt < 8; nt++) {
            sc[nt][0] *= 0.125f; sc[nt][1] *= 0.125f;
            sc[nt][2] *= 0.125f; sc[nt][3] *= 0.125f;
            mA = fmaxf(mA, fmaxf(sc[nt][0], sc[nt][1]));
            mB = fmaxf(mB, fmaxf(sc[nt][2], sc[nt][3]));
        }
        mA = fmaxf(mA, __shfl_xor_sync(0xffffffffu, mA, 1));
        mA = fmaxf(mA, __shfl_xor_sync(0xffffffffu, mA, 2));
        mB = fmaxf(mB, __shfl_xor_sync(0xffffffffu, mB, 1));
        mB = fmaxf(mB, __shfl_xor_sync(0xffffffffu, mB, 2));
        float mnA = fmaxf(m0r, mA);
        float mnB = fmaxf(m1r, mB);
        float alA = __expf(m0r - mnA);
        float alB = __expf(m1r - mnB);
        float sumA = 0.0f, sumB = 0.0f;
#pragma unroll
        for (int nt = 0; nt < 8; nt++) {
            float p0 = __expf(sc[nt][0] - mnA);
            float p1 = __expf(sc[nt][1] - mnA);
            float p2 = __expf(sc[nt][2] - mnB);
            float p3 = __expf(sc[nt][3] - mnB);
            sumA += p0 + p1;
            sumB += p2 + p3;
            __nv_bfloat162 hA = __floats2bfloat162_rn(p0, p1);
            __nv_bfloat162 hB = __floats2bfloat162_rn(p2, p3);
            *(uint32_t*)&Ps[qrowA][nt * 8 + qd * 2] = *(uint32_t*)&hA;
            *(uint32_t*)&Ps[qrowB][nt * 8 + qd * 2] = *(uint32_t*)&hB;
        }
        sumA += __shfl_xor_sync(0xffffffffu, sumA, 1);
        sumA += __shfl_xor_sync(0xffffffffu, sumA, 2);
        sumB += __shfl_xor_sync(0xffffffffu, sumB, 1);
        sumB += __shfl_xor_sync(0xffffffffu, sumB, 2);
        l0r = l0r * alA + sumA;
        l1r = l1r * alB + sumB;
        m0r = mnA;
        m1r = mnB;
#pragma unroll
        for (int nt = 0; nt < 8; nt++) {
            o[nt][0] *= alA; o[nt][1] *= alA;
            o[nt][2] *= alB; o[nt][3] *= alB;
        }
        __syncwarp();

        // ---- O += P V ----
#pragma unroll
        for (int ks = 0; ks < 4; ks++) {
            int k0 = ks * 16;
            uint32_t a0 = *(const uint32_t*)&Ps[qrowA][k0 + qd * 2];
            uint32_t a1 = *(const uint32_t*)&Ps[qrowB][k0 + qd * 2];
            uint32_t a2 = *(const uint32_t*)&Ps[qrowA][k0 + qd * 2 + 8];
            uint32_t a3 = *(const uint32_t*)&Ps[qrowB][k0 + qd * 2 + 8];
#pragma unroll
            for (int nt = 0; nt < 8; nt++) {
                uint32_t b0 = *(const uint32_t*)&Vt[nt * 8 + quad][k0 + qd * 2];
                uint32_t b1 = *(const uint32_t*)&Vt[nt * 8 + quad][k0 + qd * 2 + 8];
                mma_bf16(o[nt], a0, a1, a2, a3, b0, b1);
            }
        }
    }

    // ---- epilogue ----
    float invA = 1.0f / l0r;
    float invB = 1.0f / l1r;
    int gA = q0 + qrowA;
    int gB = q0 + qrowB;
#pragma unroll
    for (int nt = 0; nt < 8; nt++) {
        float2 vA = make_float2(o[nt][0] * invA, o[nt][1] * invA);
        float2 vB = make_float2(o[nt][2] * invB, o[nt][3] * invB);
        *(float2*)&outp[(size_t)gA * IN_DIM + head * 64 + nt * 8 + qd * 2] = vA;
        *(float2*)&outp[(size_t)gB * IN_DIM + head * 64 + nt * 8 + qd * 2] = vB;
    }
}

// ---------------- launch ----------------
extern "C" void kernel_launch(void* const* d_in, const int* in_sizes, int n_in,
                              void* d_out, int out_size) {
    const float* x          = (const float*)d_in[0];
    const int*   ei         = (const int*)d_in[1];
    const float* gcn1_w     = (const float*)d_in[2];
    const float* gcn1_b     = (const float*)d_in[3];
    const float* gcn2_w     = (const float*)d_in[4];
    const float* gcn2_b     = (const float*)d_in[5];
    const float* lin_w      = (const float*)d_in[6];
    const float* lin_b      = (const float*)d_in[7];
    const float* in_proj_w  = (const float*)d_in[8];
    const float* in_proj_b  = (const float*)d_in[9];
    const float* out_proj_w = (const float*)d_in[10];
    const float* out_proj_b = (const float*)d_in[11];
    const float* proj_w     = (const float*)d_in[12];
    const float* proj_b     = (const float*)d_in[13];
    float* out = (float*)d_out;

    // degree / normalization
    deg_init_kernel<<<NN / 256, 256>>>();
    deg_count_kernel<<<EE / 256, 256>>>(ei);
    deg_finalize_kernel<<<NN / 256, 256>>>();

    // ---- GNN branch ----
    gemm_kernel<false, false, false, false><<<dim3(HIDDEN / 64, NN / 64), 256>>>(
        x, 0L, gcn1_w, nullptr, 0L, nullptr, OFF_H1, NN, IN_DIM, HIDDEN);
    selfloop_bias_kernel<<<(NN * HIDDEN) / 256, 256>>>(OFF_H1, gcn1_b, OFF_AGG1, HIDDEN);
    scatter_kernel<<<(EE * (HIDDEN / 4)) / 256, 256>>>(OFF_H1, ei, OFF_AGG1, HIDDEN);
    relu_kernel<<<(NN * HIDDEN) / 256, 256>>>(OFF_AGG1, NN * HIDDEN);

    gemm_kernel<false, false, false, false><<<dim3(HIDDEN / 64, NN / 64), 256>>>(
        nullptr, OFF_AGG1, gcn2_w, nullptr, 0L, nullptr, OFF_H2, NN, HIDDEN, HIDDEN);
    selfloop_bias_kernel<<<(NN * HIDDEN) / 256, 256>>>(OFF_H2, gcn2_b, OFF_AGG2, HIDDEN);
    scatter_kernel<<<(EE * (HIDDEN / 4)) / 256, 256>>>(OFF_H2, ei, OFF_AGG2, HIDDEN);
    relu_kernel<<<(NN * HIDDEN) / 256, 256>>>(OFF_AGG2, NN * HIDDEN);

    gemm_kernel<false, false, true, false><<<dim3(CLASSES / 64, NN / 64), 256>>>(
        nullptr, OFF_AGG2, lin_w, lin_b, 0L, nullptr, OFF_GNN, NN, HIDDEN, CLASSES);

    // ---- Transformer branch ----
    gemm_kernel<true, false, true, false><<<dim3((3 * IN_DIM) / 64, NN / 64), 256>>>(
        x, 0L, in_proj_w, in_proj_b, 0L, nullptr, OFF_QKV, NN, IN_DIM, 3 * IN_DIM);

    cvt_qkv_kernel<<<(NN * 768 / 2) / 256, 256>>>();
    flash_attn_bf16_kernel<<<dim3(NN / 64, HEADS), 128>>>();

    gemm_kernel<true, false, true, false><<<dim3(IN_DIM / 64, NN / 64), 256>>>(
        nullptr, OFF_ATTN, out_proj_w, out_proj_b, 0L, nullptr, OFF_XTF, NN, IN_DIM, IN_DIM);

    gemm_kernel<false, true, true, true><<<dim3(CLASSES / 64, NN / 64), 256>>>(
        nullptr, OFF_XTF, proj_w, proj_b, OFF_GNN, out, 0L, NN, IN_DIM, CLASSES);
}